// round 7
// baseline (speedup 1.0000x reference)
#include <cuda_runtime.h>

#define NQ   10
#define DIM  1024
#define NL   4
#define NOUT 16
#define TPB  128

typedef unsigned long long ull;

// Scratch (allocation-free rule: __device__ globals)
__device__ ull            g_gates[NL * NQ * 8];   // 40 gates x 7 broadcast f32x2 packs (+pad)
__device__ unsigned short g_scat[NL][DIM];        // scatter table: old-logical idx -> swz(new idx)

// 16B-granule bank swizzle, bijective on [0,1024); keeps bit 0 intact.
__device__ __forceinline__ int swz(int i) { return i ^ (((i >> 4) & 7) << 1); }

// ---- f32x2 packed helpers ----
__device__ __forceinline__ ull pk(float lo, float hi) {
    ull r; asm("mov.b64 %0, {%1, %2};" : "=l"(r) : "f"(lo), "f"(hi)); return r;
}
__device__ __forceinline__ void upk(ull v, float& lo, float& hi) {
    asm("mov.b64 {%0, %1}, %2;" : "=f"(lo), "=f"(hi) : "l"(v));
}
__device__ __forceinline__ ull mul2(ull a, ull b) {
    ull d; asm("mul.rn.f32x2 %0, %1, %2;" : "=l"(d) : "l"(a), "l"(b)); return d;
}
__device__ __forceinline__ ull fma2(ull a, ull b, ull c) {
    ull d; asm("fma.rn.f32x2 %0, %1, %2, %3;" : "=l"(d) : "l"(a), "l"(b), "l"(c)); return d;
}
__device__ __forceinline__ ull add2(ull a, ull b) {
    ull d; asm("add.rn.f32x2 %0, %1, %2;" : "=l"(d) : "l"(a), "l"(b)); return d;
}
__device__ __forceinline__ ull neg2(ull a) { return a ^ 0x8000000080000000ULL; }

// ---------------------------------------------------------------------------
// Init: broadcast gate packs + CNOT scatter tables.
// state_new[j] = state_old[perm(j)]  =>  value at old idx i stores to
// swz(j) where perm(j)=i  =>  g_scat[l][perm(j)] = swz(j).
// SU(2): d = conj(a), c = -conj(b)  ->  7 packs per gate.
// ---------------------------------------------------------------------------
__global__ void vqc_init(const float* __restrict__ wts) {
    int l = blockIdx.x;
    int r = l % (NQ - 1) + 1;
    for (int j = threadIdx.x; j < DIM; j += blockDim.x) {
        int t = j;
        #pragma unroll
        for (int q = NQ - 1; q >= 0; --q) {
            int pc = NQ - 1 - q;
            int pt = NQ - 1 - ((q + r) % NQ);
            t ^= ((t >> pc) & 1) << pt;
        }
        g_scat[l][t] = (unsigned short)swz(j);
    }
    if (l == 0 && threadIdx.x < NL * NQ) {
        int idx   = threadIdx.x;
        float phi = wts[idx * 3 + 0];
        float th  = wts[idx * 3 + 1];
        float om  = wts[idx * 3 + 2];
        float sh, ch;   sincosf(0.5f * th, &sh, &ch);
        float ssp, csp; sincosf(0.5f * (phi + om), &ssp, &csp);
        float ssm, csm; sincosf(0.5f * (phi - om), &ssm, &csm);
        float ar =  csp * ch, ai = -ssp * ch;   // a = e^{-i(phi+om)/2} cos
        float br = -csm * sh, bi = -ssm * sh;   // b = -e^{ i(phi-om)/2} sin
        ull* g = &g_gates[idx * 8];
        g[0] = pk(ar, ar);   g[1] = pk(ai, ai);
        g[2] = pk(br, br);   g[3] = pk(bi, bi);
        g[4] = pk(-ai, -ai); g[5] = pk(-bi, -bi);
        g[6] = pk(-br, -br); g[7] = 0ULL;
    }
}

// Complex 2x2 SU(2) gate on batch-packed pair: 16 FFMA2, no MOVs.
__device__ __forceinline__ void cgate(ull G0, ull G1, ull G2, ull G3,
                                      ull G4, ull G5, ull G6,
                                      ull& xr, ull& xi, ull& yr, ull& yi) {
    ull oxr = fma2(G5, yi, fma2(G2, yr, fma2(G4, xi, mul2(G0, xr))));
    ull oxi = fma2(G2, yi, fma2(G3, yr, fma2(G0, xi, mul2(G1, xr))));
    ull oyr = fma2(G1, yi, fma2(G0, yr, fma2(G5, xi, mul2(G6, xr))));
    ull oyi = fma2(G0, yi, fma2(G4, yr, fma2(G6, xi, mul2(G3, xr))));
    xr = oxr; xi = oxi; yr = oyr; yi = oyi;
}

// Apply gate `gid` to local k-bit m over the 8-amp register tile
#define APPLY(gid, m)                                                          \
    do {                                                                       \
        const ull* _G = &gsm[(gid) * 8];                                       \
        ull _G0=_G[0],_G1=_G[1],_G2=_G[2],_G3=_G[3],_G4=_G[4],_G5=_G[5],_G6=_G[6]; \
        _Pragma("unroll")                                                      \
        for (int _p = 0; _p < 4; ++_p) {                                       \
            int _i = ((_p >> (m)) << ((m) + 1)) | (_p & ((1 << (m)) - 1));     \
            int _j = _i | (1 << (m));                                          \
            cgate(_G0,_G1,_G2,_G3,_G4,_G5,_G6, re[_i], im[_i], re[_j], im[_j]);\
        }                                                                      \
    } while (0)

// Gate on lane bit 0 (qubit 9) via warp shuffle; each thread computes its half.
#define APPLY_SHFL(gid)                                                        \
    do {                                                                       \
        const ull* _G = &gsm[(gid) * 8];                                       \
        int _s = tid & 1;                                                      \
        ull _c1r = _G[0];                                                      \
        ull _c1i = _s ? _G[4] : _G[1];                                         \
        ull _n1i = _s ? _G[1] : _G[4];                                         \
        ull _c2r = _s ? _G[6] : _G[2];                                         \
        ull _c2i = _G[3], _n2i = _G[5];                                        \
        _Pragma("unroll")                                                      \
        for (int _k = 0; _k < 8; ++_k) {                                       \
            ull _vr = re[_k], _vi = im[_k];                                    \
            ull _ur = __shfl_xor_sync(0xffffffffu, _vr, 1);                    \
            ull _ui = __shfl_xor_sync(0xffffffffu, _vi, 1);                    \
            re[_k] = fma2(_n2i,_ui, fma2(_c2r,_ur, fma2(_n1i,_vi, mul2(_c1r,_vr)))); \
            im[_k] = fma2(_c2i,_ur, fma2(_c2r,_ui, fma2(_c1i,_vr, mul2(_c1r,_vi)))); \
        }                                                                      \
    } while (0)

__global__ void __launch_bounds__(TPB, 8) vqc_main(
    const float* __restrict__ X,
    const float* __restrict__ W,
    const float* __restrict__ bias,
    float* __restrict__ out)
{
    __shared__ ulonglong2 st[DIM];           // batch-pair state (16 KB), swizzled
    __shared__ ull        gsm[NL * NQ * 8];  // gate packs (2.5 KB)
    __shared__ ull        zw[4][NQ];
    __shared__ ull        zsh[NQ];
    __shared__ float      red2[4][2];
    __shared__ float      s_inv[2];

    const int tid  = threadIdx.x;
    const int b    = blockIdx.x;
    const int lane = tid & 31, warp = tid >> 5;

    for (int i = tid; i < NL * NQ * 8; i += TPB) gsm[i] = g_gates[i];

    ull re[8], im[8];
    const ull zero = pk(0.f, 0.f);

    // ---- load two X rows in pattern A (bits 9..7 = k), coalesced
    {
        const float* X0 = X + (size_t)(2 * b) * DIM;
        const float* X1 = X0 + DIM;
        ull ss2 = zero;
        #pragma unroll
        for (int k = 0; k < 8; ++k) {
            int idx = (k << 7) | tid;
            re[k] = pk(X0[idx], X1[idx]);
            im[k] = zero;
            ss2 = fma2(re[k], re[k], ss2);
        }
        float s0, s1; upk(ss2, s0, s1);
        #pragma unroll
        for (int o = 16; o > 0; o >>= 1) {
            s0 += __shfl_xor_sync(0xffffffffu, s0, o);
            s1 += __shfl_xor_sync(0xffffffffu, s1, o);
        }
        if (lane == 0) { red2[warp][0] = s0; red2[warp][1] = s1; }
    }
    __syncthreads();   // gsm + red2 visible
    if (tid == 0) {
        s_inv[0] = 1.f / (red2[0][0] + red2[1][0] + red2[2][0] + red2[3][0]);
        s_inv[1] = 1.f / (red2[0][1] + red2[1][1] + red2[2][1] + red2[3][1]);
    }

    #pragma unroll
    for (int l = 0; l < NL; ++l) {
        const int gb = l * NQ;
        // ---- round A: qubits 0..2 (bits 9..7 = k); plain gather (perm was
        //      applied at previous layer's round-C scatter). Gather/scatter use
        //      the SAME per-thread addresses -> no internal barrier needed.
        if (l == 0) {
            APPLY(gb + 0, 2); APPLY(gb + 1, 1); APPLY(gb + 2, 0);
            #pragma unroll
            for (int k = 0; k < 8; ++k)
                st[swz((k << 7) | tid)] = make_ulonglong2(re[k], im[k]);
        } else {
            __syncthreads();          // prev round-C perm scatter visible
            #pragma unroll
            for (int k = 0; k < 8; ++k) {
                ulonglong2 v = st[swz((k << 7) | tid)];
                re[k] = v.x; im[k] = v.y;
            }
            APPLY(gb + 0, 2); APPLY(gb + 1, 1); APPLY(gb + 2, 0);
            #pragma unroll
            for (int k = 0; k < 8; ++k)
                st[swz((k << 7) | tid)] = make_ulonglong2(re[k], im[k]);
        }
        // ---- round B: qubits 3..5 (bits 6..4 = k)
        __syncthreads();
        #pragma unroll
        for (int k = 0; k < 8; ++k) {
            ulonglong2 v = st[swz(((tid >> 4) << 7) | (k << 4) | (tid & 15))];
            re[k] = v.x; im[k] = v.y;
        }
        APPLY(gb + 3, 2); APPLY(gb + 4, 1); APPLY(gb + 5, 0);
        #pragma unroll
        for (int k = 0; k < 8; ++k)
            st[swz(((tid >> 4) << 7) | (k << 4) | (tid & 15))] = make_ulonglong2(re[k], im[k]);

        // ---- round C: qubits 6..8 (bits 3..1 = k), qubit 9 (bit 0) via shfl;
        //      CNOT layer folded into the scatter addresses.
        __syncthreads();
        #pragma unroll
        for (int k = 0; k < 8; ++k) {
            ulonglong2 v = st[swz(((tid >> 1) << 4) | (k << 1) | (tid & 1))];
            re[k] = v.x; im[k] = v.y;
        }
        APPLY(gb + 6, 2); APPLY(gb + 7, 1); APPLY(gb + 8, 0);
        APPLY_SHFL(gb + 9);
        __syncthreads();              // all round-C gathers done before perm scatter
        #pragma unroll
        for (int k = 0; k < 8; ++k)
            st[g_scat[l][((tid >> 1) << 4) | (k << 1) | (tid & 1)]] =
                make_ulonglong2(re[k], im[k]);
    }
    __syncthreads();

    // ---- PauliZ expectations; state already fully permuted -> plain gather
    ull p[8];
    #pragma unroll
    for (int k = 0; k < 8; ++k) {
        ulonglong2 v = st[swz((k << 7) | tid)];
        p[k] = fma2(v.y, v.y, mul2(v.x, v.x));
    }
    ull T = p[0];
    #pragma unroll
    for (int k = 1; k < 8; ++k) T = add2(T, p[k]);

    ull z[NQ];
    const ull mtwo = pk(-2.f, -2.f);
    #pragma unroll
    for (int q = 0; q < 3; ++q) {            // qubits 0..2 = k bits 2..0
        int bit = 2 - q;
        ull S = zero;
        #pragma unroll
        for (int k = 0; k < 8; ++k)
            if ((k >> bit) & 1) S = add2(S, p[k]);
        z[q] = fma2(mtwo, S, T);             // T - 2*S
    }
    ull nT = neg2(T);
    #pragma unroll
    for (int q = 3; q < NQ; ++q)             // qubits 3..9 = tid bits 6..0
        z[q] = ((tid >> (9 - q)) & 1) ? nT : T;

    #pragma unroll
    for (int q = 0; q < NQ; ++q) {
        #pragma unroll
        for (int o = 16; o > 0; o >>= 1)
            z[q] = add2(z[q], __shfl_xor_sync(0xffffffffu, z[q], o));
        if (lane == 0) zw[warp][q] = z[q];
    }
    __syncthreads();
    if (tid < NQ)
        zsh[tid] = add2(add2(zw[0][tid], zw[1][tid]), add2(zw[2][tid], zw[3][tid]));
    __syncthreads();

    // ---- linear head: 2 batches x 16 outputs on threads 0..31
    if (tid < 32) {
        int bl = tid >> 4, o = tid & 15;
        float inv = s_inv[bl];
        float acc = bias[o];
        #pragma unroll
        for (int q = 0; q < NQ; ++q) {
            float zl, zh; upk(zsh[q], zl, zh);
            acc += inv * (bl ? zh : zl) * W[o * NQ + q];
        }
        out[(size_t)(2 * b + bl) * NOUT + o] = acc;
    }
}

extern "C" void kernel_launch(void* const* d_in, const int* in_sizes, int n_in,
                              void* d_out, int out_size) {
    const float* X    = (const float*)d_in[0];   // (BATCH, 1024) f32
    const float* wts  = (const float*)d_in[1];   // (4, 10, 3) f32
    const float* W    = (const float*)d_in[2];   // (16, 10) f32
    const float* bias = (const float*)d_in[3];   // (16,) f32
    float* out = (float*)d_out;                  // (BATCH, 16) f32

    int batch = in_sizes[0] / DIM;
    vqc_init<<<NL, 256>>>(wts);
    vqc_main<<<batch / 2, TPB>>>(X, W, bias, out);
}

// round 11
// speedup vs baseline: 1.0845x; 1.0845x over previous
#include <cuda_runtime.h>

#define NQ   10
#define DIM  1024
#define NL   4
#define NOUT 16
#define TPB  128

typedef unsigned long long ull;

// Scratch (allocation-free rule: __device__ globals)
__device__ ulonglong2     g_gates[NL * NQ * 2];   // 40 gates x 4 broadcast f32x2 packs
__device__ unsigned short g_perm[NL][DIM];        // per-layer perm, PRE-SWIZZLED values

// 16B-granule bank swizzle, bijective on [0,1024); keeps bit 0 intact.
__device__ __forceinline__ int swz(int i) { return i ^ (((i >> 4) & 7) << 1); }

// ---- f32x2 packed helpers ----
__device__ __forceinline__ ull pk(float lo, float hi) {
    ull r; asm("mov.b64 %0, {%1, %2};" : "=l"(r) : "f"(lo), "f"(hi)); return r;
}
__device__ __forceinline__ void upk(ull v, float& lo, float& hi) {
    asm("mov.b64 {%0, %1}, %2;" : "=f"(lo), "=f"(hi) : "l"(v));
}
__device__ __forceinline__ ull mul2(ull a, ull b) {
    ull d; asm("mul.rn.f32x2 %0, %1, %2;" : "=l"(d) : "l"(a), "l"(b)); return d;
}
__device__ __forceinline__ ull fma2(ull a, ull b, ull c) {
    ull d; asm("fma.rn.f32x2 %0, %1, %2, %3;" : "=l"(d) : "l"(a), "l"(b), "l"(c)); return d;
}
__device__ __forceinline__ ull add2(ull a, ull b) {
    ull d; asm("add.rn.f32x2 %0, %1, %2;" : "=l"(d) : "l"(a), "l"(b)); return d;
}
__device__ __forceinline__ ull neg2(ull a) { return a ^ 0x8000000080000000ULL; }

// ---------------------------------------------------------------------------
// Init: 4 broadcast packs per gate + pre-swizzled CNOT permutation tables.
// SU(2): d = conj(a), c = -conj(b); negated packs derived in-kernel by XOR.
//   pack0 = {(ar,ar),(ai,ai)}   pack1 = {(br,br),(bi,bi)}
// ---------------------------------------------------------------------------
__global__ void vqc_init(const float* __restrict__ wts) {
    int l = blockIdx.x;
    int r = l % (NQ - 1) + 1;
    for (int j = threadIdx.x; j < DIM; j += blockDim.x) {
        int t = j;
        #pragma unroll
        for (int q = NQ - 1; q >= 0; --q) {
            int pc = NQ - 1 - q;
            int pt = NQ - 1 - ((q + r) % NQ);
            t ^= ((t >> pc) & 1) << pt;
        }
        g_perm[l][j] = (unsigned short)swz(t);   // pre-swizzled
    }
    if (l == 0 && threadIdx.x < NL * NQ) {
        int idx   = threadIdx.x;
        float phi = wts[idx * 3 + 0];
        float th  = wts[idx * 3 + 1];
        float om  = wts[idx * 3 + 2];
        float sh, ch;   sincosf(0.5f * th, &sh, &ch);
        float ssp, csp; sincosf(0.5f * (phi + om), &ssp, &csp);
        float ssm, csm; sincosf(0.5f * (phi - om), &ssm, &csm);
        float ar =  csp * ch, ai = -ssp * ch;   // a = e^{-i(phi+om)/2} cos
        float br = -csm * sh, bi = -ssm * sh;   // b = -e^{ i(phi-om)/2} sin
        g_gates[idx * 2 + 0] = make_ulonglong2(pk(ar, ar), pk(ai, ai));
        g_gates[idx * 2 + 1] = make_ulonglong2(pk(br, br), pk(bi, bi));
    }
}

// Complex 2x2 SU(2) gate on batch-packed pair: 16 FFMA2.
// N1=-G1, N2=-G2, N3=-G3 (hoisted per-gate).
__device__ __forceinline__ void cgate(ull G0, ull G1, ull G2, ull G3,
                                      ull N1, ull N2, ull N3,
                                      ull& xr, ull& xi, ull& yr, ull& yi) {
    ull oxr = fma2(N3, yi, fma2(G2, yr, fma2(N1, xi, mul2(G0, xr))));
    ull oxi = fma2(G2, yi, fma2(G3, yr, fma2(G0, xi, mul2(G1, xr))));
    ull oyr = fma2(G1, yi, fma2(G0, yr, fma2(N3, xi, mul2(N2, xr))));
    ull oyi = fma2(G0, yi, fma2(N1, yr, fma2(N2, xi, mul2(G3, xr))));
    xr = oxr; xi = oxi; yr = oyr; yi = oyi;
}

// Apply gate `gid` to local k-bit m over the 8-amp register tile.
// 2 x LDS.128 coefficient load + 3 XOR derivation.
#define APPLY(gid, m)                                                          \
    do {                                                                       \
        ulonglong2 _u0 = gsm[(gid) * 2], _u1 = gsm[(gid) * 2 + 1];             \
        ull _G0 = _u0.x, _G1 = _u0.y, _G2 = _u1.x, _G3 = _u1.y;                \
        ull _N1 = neg2(_G1), _N2 = neg2(_G2), _N3 = neg2(_G3);                 \
        _Pragma("unroll")                                                      \
        for (int _p = 0; _p < 4; ++_p) {                                       \
            int _i = ((_p >> (m)) << ((m) + 1)) | (_p & ((1 << (m)) - 1));     \
            int _j = _i | (1 << (m));                                          \
            cgate(_G0,_G1,_G2,_G3,_N1,_N2,_N3, re[_i], im[_i], re[_j], im[_j]);\
        }                                                                      \
    } while (0)

// Gate on lane bit 0 (qubit 9) via warp shuffle; each thread computes its half.
#define APPLY_SHFL(gid)                                                        \
    do {                                                                       \
        ulonglong2 _u0 = gsm[(gid) * 2], _u1 = gsm[(gid) * 2 + 1];             \
        ull _G0 = _u0.x, _G1 = _u0.y, _G2 = _u1.x, _G3 = _u1.y;                \
        ull _N1 = neg2(_G1), _N2 = neg2(_G2), _N3 = neg2(_G3);                 \
        int _s = tid & 1;                                                      \
        ull _c1r = _G0;                                                        \
        ull _c1i = _s ? _N1 : _G1;                                             \
        ull _n1i = _s ? _G1 : _N1;                                             \
        ull _c2r = _s ? _N2 : _G2;                                             \
        ull _c2i = _G3, _n2i = _N3;                                            \
        _Pragma("unroll")                                                      \
        for (int _k = 0; _k < 8; ++_k) {                                       \
            ull _vr = re[_k], _vi = im[_k];                                    \
            ull _ur = __shfl_xor_sync(0xffffffffu, _vr, 1);                    \
            ull _ui = __shfl_xor_sync(0xffffffffu, _vi, 1);                    \
            re[_k] = fma2(_n2i,_ui, fma2(_c2r,_ur, fma2(_n1i,_vi, mul2(_c1r,_vr)))); \
            im[_k] = fma2(_c2i,_ur, fma2(_c2r,_ui, fma2(_c1i,_vr, mul2(_c1r,_vi)))); \
        }                                                                      \
    } while (0)

__global__ void __launch_bounds__(TPB, 7) vqc_main(
    const float* __restrict__ X,
    const float* __restrict__ W,
    const float* __restrict__ bias,
    float* __restrict__ out)
{
    __shared__ ulonglong2 st[DIM];            // batch-pair state (16 KB), swizzled
    __shared__ ulonglong2 gsm[NL * NQ * 2];   // gate packs (1.25 KB)
    __shared__ ull        zw[4][NQ];
    __shared__ ull        zsh[NQ];
    __shared__ float      red2[4][2];
    __shared__ float      s_inv[2];

    const int tid  = threadIdx.x;
    const int b    = blockIdx.x;
    const int lane = tid & 31, warp = tid >> 5;

    for (int i = tid; i < NL * NQ * 2; i += TPB) gsm[i] = g_gates[i];

    ull re[8], im[8];
    const ull zero = pk(0.f, 0.f);

    // ---- load two X rows in pattern A (bits 9..7 = k), coalesced
    {
        const float* X0 = X + (size_t)(2 * b) * DIM;
        const float* X1 = X0 + DIM;
        ull ss2 = zero;
        #pragma unroll
        for (int k = 0; k < 8; ++k) {
            int idx = (k << 7) | tid;
            re[k] = pk(X0[idx], X1[idx]);
            im[k] = zero;
            ss2 = fma2(re[k], re[k], ss2);
        }
        float s0, s1; upk(ss2, s0, s1);
        #pragma unroll
        for (int o = 16; o > 0; o >>= 1) {
            s0 += __shfl_xor_sync(0xffffffffu, s0, o);
            s1 += __shfl_xor_sync(0xffffffffu, s1, o);
        }
        if (lane == 0) { red2[warp][0] = s0; red2[warp][1] = s1; }
    }
    __syncthreads();   // gsm + red2 visible
    if (tid == 0) {
        s_inv[0] = 1.f / (red2[0][0] + red2[1][0] + red2[2][0] + red2[3][0]);
        s_inv[1] = 1.f / (red2[0][1] + red2[1][1] + red2[2][1] + red2[3][1]);
    }

    #pragma unroll
    for (int l = 0; l < NL; ++l) {
        const int gb = l * NQ;
        // ---- round A: qubits 0..2 (bits 9..7 = k); CNOT of prev layer folded
        //      into the gather addresses. m=0 gate first (data-ready order).
        if (l == 0) {
            APPLY(gb + 2, 0); APPLY(gb + 1, 1); APPLY(gb + 0, 2);
            #pragma unroll
            for (int k = 0; k < 8; ++k)
                st[swz((k << 7) | tid)] = make_ulonglong2(re[k], im[k]);
        } else {
            __syncthreads();          // prev layer's round-C stores visible
            #pragma unroll
            for (int k = 0; k < 8; ++k) {
                ulonglong2 v = st[g_perm[l - 1][(k << 7) | tid]];  // CNOT folded
                re[k] = v.x; im[k] = v.y;
            }
            APPLY(gb + 2, 0); APPLY(gb + 1, 1); APPLY(gb + 0, 2);
            __syncthreads();          // all gathers done before overwrite
            #pragma unroll
            for (int k = 0; k < 8; ++k)
                st[swz((k << 7) | tid)] = make_ulonglong2(re[k], im[k]);
        }
        // ---- round B: qubits 3..5 (bits 6..4 = k)
        __syncthreads();
        #pragma unroll
        for (int k = 0; k < 8; ++k) {
            ulonglong2 v = st[swz(((tid >> 4) << 7) | (k << 4) | (tid & 15))];
            re[k] = v.x; im[k] = v.y;
        }
        APPLY(gb + 5, 0); APPLY(gb + 4, 1); APPLY(gb + 3, 2);
        #pragma unroll
        for (int k = 0; k < 8; ++k)
            st[swz(((tid >> 4) << 7) | (k << 4) | (tid & 15))] = make_ulonglong2(re[k], im[k]);

        // ---- round C: qubits 6..8 (bits 3..1 = k), qubit 9 (bit 0) via shfl
        __syncthreads();
        #pragma unroll
        for (int k = 0; k < 8; ++k) {
            ulonglong2 v = st[swz(((tid >> 1) << 4) | (k << 1) | (tid & 1))];
            re[k] = v.x; im[k] = v.y;
        }
        APPLY(gb + 8, 0); APPLY(gb + 7, 1); APPLY(gb + 6, 2);
        APPLY_SHFL(gb + 9);
        #pragma unroll
        for (int k = 0; k < 8; ++k)
            st[swz(((tid >> 1) << 4) | (k << 1) | (tid & 1))] = make_ulonglong2(re[k], im[k]);
    }
    __syncthreads();

    // ---- PauliZ expectations; layer-3 perm folded into gather (pattern A)
    ull p[8];
    #pragma unroll
    for (int k = 0; k < 8; ++k) {
        ulonglong2 v = st[g_perm[NL - 1][(k << 7) | tid]];
        p[k] = fma2(v.y, v.y, mul2(v.x, v.x));
    }
    ull T = p[0];
    #pragma unroll
    for (int k = 1; k < 8; ++k) T = add2(T, p[k]);

    ull z[NQ];
    const ull mtwo = pk(-2.f, -2.f);
    #pragma unroll
    for (int q = 0; q < 3; ++q) {            // qubits 0..2 = k bits 2..0
        int bit = 2 - q;
        ull S = zero;
        #pragma unroll
        for (int k = 0; k < 8; ++k)
            if ((k >> bit) & 1) S = add2(S, p[k]);
        z[q] = fma2(mtwo, S, T);             // T - 2*S
    }
    ull nT = neg2(T);
    #pragma unroll
    for (int q = 3; q < NQ; ++q)             // qubits 3..9 = tid bits 6..0
        z[q] = ((tid >> (9 - q)) & 1) ? nT : T;

    #pragma unroll
    for (int q = 0; q < NQ; ++q) {
        #pragma unroll
        for (int o = 16; o > 0; o >>= 1)
            z[q] = add2(z[q], __shfl_xor_sync(0xffffffffu, z[q], o));
        if (lane == 0) zw[warp][q] = z[q];
    }
    __syncthreads();
    if (tid < NQ)
        zsh[tid] = add2(add2(zw[0][tid], zw[1][tid]), add2(zw[2][tid], zw[3][tid]));
    __syncthreads();

    // ---- linear head: 2 batches x 16 outputs on threads 0..31
    if (tid < 32) {
        int bl = tid >> 4, o = tid & 15;
        float inv = s_inv[bl];
        float acc = bias[o];
        #pragma unroll
        for (int q = 0; q < NQ; ++q) {
            float zl, zh; upk(zsh[q], zl, zh);
            acc += inv * (bl ? zh : zl) * W[o * NQ + q];
        }
        out[(size_t)(2 * b + bl) * NOUT + o] = acc;
    }
}

extern "C" void kernel_launch(void* const* d_in, const int* in_sizes, int n_in,
                              void* d_out, int out_size) {
    const float* X    = (const float*)d_in[0];   // (BATCH, 1024) f32
    const float* wts  = (const float*)d_in[1];   // (4, 10, 3) f32
    const float* W    = (const float*)d_in[2];   // (16, 10) f32
    const float* bias = (const float*)d_in[3];   // (16,) f32
    float* out = (float*)d_out;                  // (BATCH, 16) f32

    int batch = in_sizes[0] / DIM;
    vqc_init<<<NL, 256>>>(wts);
    vqc_main<<<batch / 2, TPB>>>(X, W, bias, out);
}

// round 15
// speedup vs baseline: 1.1182x; 1.0310x over previous
#include <cuda_runtime.h>

#define NQ   10
#define DIM  1024
#define NL   4
#define NOUT 16
#define TPB  128

typedef unsigned long long ull;

// Scratch (allocation-free rule: __device__ globals)
__device__ ulonglong2     g_gates[NL * NQ * 4];   // 40 gates x 8 packs: G0..G3,N1..N3,pad
__device__ unsigned short g_perm[NL][DIM];        // per-layer perm, PRE-SWIZZLED values

// 16B-granule bank swizzle, bijective on [0,1024); touches only bits 1..3.
__device__ __forceinline__ int swz(int i) { return i ^ (((i >> 4) & 7) << 1); }

// ---- f32x2 packed helpers ----
__device__ __forceinline__ ull pk(float lo, float hi) {
    ull r; asm("mov.b64 %0, {%1, %2};" : "=l"(r) : "f"(lo), "f"(hi)); return r;
}
__device__ __forceinline__ void upk(ull v, float& lo, float& hi) {
    asm("mov.b64 {%0, %1}, %2;" : "=f"(lo), "=f"(hi) : "l"(v));
}
__device__ __forceinline__ ull mul2(ull a, ull b) {
    ull d; asm("mul.rn.f32x2 %0, %1, %2;" : "=l"(d) : "l"(a), "l"(b)); return d;
}
__device__ __forceinline__ ull fma2(ull a, ull b, ull c) {
    ull d; asm("fma.rn.f32x2 %0, %1, %2, %3;" : "=l"(d) : "l"(a), "l"(b), "l"(c)); return d;
}
__device__ __forceinline__ ull add2(ull a, ull b) {
    ull d; asm("add.rn.f32x2 %0, %1, %2;" : "=l"(d) : "l"(a), "l"(b)); return d;
}
__device__ __forceinline__ ull neg2(ull a) { return a ^ 0x8000000080000000ULL; }

// ---------------------------------------------------------------------------
// Init: 8 broadcast packs per gate (negatives precomputed) + pre-swizzled
// CNOT permutation tables.
// SU(2): d = conj(a), c = -conj(b).
// ---------------------------------------------------------------------------
__global__ void vqc_init(const float* __restrict__ wts) {
    int l = blockIdx.x;
    int r = l % (NQ - 1) + 1;
    for (int j = threadIdx.x; j < DIM; j += blockDim.x) {
        int t = j;
        #pragma unroll
        for (int q = NQ - 1; q >= 0; --q) {
            int pc = NQ - 1 - q;
            int pt = NQ - 1 - ((q + r) % NQ);
            t ^= ((t >> pc) & 1) << pt;
        }
        g_perm[l][j] = (unsigned short)swz(t);   // pre-swizzled
    }
    if (l == 0 && threadIdx.x < NL * NQ) {
        int idx   = threadIdx.x;
        float phi = wts[idx * 3 + 0];
        float th  = wts[idx * 3 + 1];
        float om  = wts[idx * 3 + 2];
        float sh, ch;   sincosf(0.5f * th, &sh, &ch);
        float ssp, csp; sincosf(0.5f * (phi + om), &ssp, &csp);
        float ssm, csm; sincosf(0.5f * (phi - om), &ssm, &csm);
        float ar =  csp * ch, ai = -ssp * ch;   // a = e^{-i(phi+om)/2} cos
        float br = -csm * sh, bi = -ssm * sh;   // b = -e^{ i(phi-om)/2} sin
        g_gates[idx * 4 + 0] = make_ulonglong2(pk(ar, ar), pk(ai, ai));
        g_gates[idx * 4 + 1] = make_ulonglong2(pk(br, br), pk(bi, bi));
        g_gates[idx * 4 + 2] = make_ulonglong2(pk(-ai, -ai), pk(-br, -br));
        g_gates[idx * 4 + 3] = make_ulonglong2(pk(-bi, -bi), 0ULL);
    }
}

// Complex 2x2 SU(2) gate on batch-packed pair: 16 FFMA2.
__device__ __forceinline__ void cgate(ull G0, ull G1, ull G2, ull G3,
                                      ull N1, ull N2, ull N3,
                                      ull& xr, ull& xi, ull& yr, ull& yi) {
    ull oxr = fma2(N3, yi, fma2(G2, yr, fma2(N1, xi, mul2(G0, xr))));
    ull oxi = fma2(G2, yi, fma2(G3, yr, fma2(G0, xi, mul2(G1, xr))));
    ull oyr = fma2(G1, yi, fma2(G0, yr, fma2(N3, xi, mul2(N2, xr))));
    ull oyi = fma2(G0, yi, fma2(N1, yr, fma2(N2, xi, mul2(G3, xr))));
    xr = oxr; xi = oxi; yr = oyr; yi = oyi;
}

// Apply gate `gid` to local k-bit m over the 8-amp register tile.
// 4 x LDS.128 broadcast coefficient load, no derivation math.
#define APPLY(gid, m)                                                          \
    do {                                                                       \
        ulonglong2 _u0 = gsm[(gid) * 4 + 0], _u1 = gsm[(gid) * 4 + 1];         \
        ulonglong2 _u2 = gsm[(gid) * 4 + 2], _u3 = gsm[(gid) * 4 + 3];         \
        ull _G0 = _u0.x, _G1 = _u0.y, _G2 = _u1.x, _G3 = _u1.y;                \
        ull _N1 = _u2.x, _N2 = _u2.y, _N3 = _u3.x;                             \
        _Pragma("unroll")                                                      \
        for (int _p = 0; _p < 4; ++_p) {                                       \
            int _i = ((_p >> (m)) << ((m) + 1)) | (_p & ((1 << (m)) - 1));     \
            int _j = _i | (1 << (m));                                          \
            cgate(_G0,_G1,_G2,_G3,_N1,_N2,_N3, re[_i], im[_i], re[_j], im[_j]);\
        }                                                                      \
    } while (0)

// Gate on lane bit 0 (qubit 9) via warp shuffle; each thread computes its half.
#define APPLY_SHFL(gid)                                                        \
    do {                                                                       \
        ulonglong2 _u0 = gsm[(gid) * 4 + 0], _u1 = gsm[(gid) * 4 + 1];         \
        ulonglong2 _u2 = gsm[(gid) * 4 + 2], _u3 = gsm[(gid) * 4 + 3];         \
        ull _G0 = _u0.x, _G1 = _u0.y, _G2 = _u1.x, _G3 = _u1.y;                \
        ull _N1 = _u2.x, _N2 = _u2.y, _N3 = _u3.x;                             \
        int _s = tid & 1;                                                      \
        ull _c1r = _G0;                                                        \
        ull _c1i = _s ? _N1 : _G1;                                             \
        ull _n1i = _s ? _G1 : _N1;                                             \
        ull _c2r = _s ? _N2 : _G2;                                             \
        ull _c2i = _G3, _n2i = _N3;                                            \
        _Pragma("unroll")                                                      \
        for (int _k = 0; _k < 8; ++_k) {                                       \
            ull _vr = re[_k], _vi = im[_k];                                    \
            ull _ur = __shfl_xor_sync(0xffffffffu, _vr, 1);                    \
            ull _ui = __shfl_xor_sync(0xffffffffu, _vi, 1);                    \
            re[_k] = fma2(_n2i,_ui, fma2(_c2r,_ur, fma2(_n1i,_vi, mul2(_c1r,_vr)))); \
            im[_k] = fma2(_c2i,_ur, fma2(_c2r,_ui, fma2(_c1i,_vr, mul2(_c1r,_vi)))); \
        }                                                                      \
    } while (0)

__global__ void __launch_bounds__(TPB, 7) vqc_main(
    const float* __restrict__ X,
    const float* __restrict__ W,
    const float* __restrict__ bias,
    float* __restrict__ out)
{
    __shared__ ulonglong2 st[DIM];            // batch-pair state (16 KB), swizzled
    __shared__ ulonglong2 gsm[NL * NQ * 4];   // gate packs (2.5 KB)
    __shared__ ull        zw[4][NQ];
    __shared__ ull        zsh[NQ];
    __shared__ float      red2[4][2];
    __shared__ float      s_inv[2];

    const int tid  = threadIdx.x;
    const int b    = blockIdx.x;
    const int lane = tid & 31, warp = tid >> 5;

    for (int i = tid; i < NL * NQ * 4; i += TPB) gsm[i] = g_gates[i];

    ull re[8], im[8];
    const ull zero = pk(0.f, 0.f);

    // ---- load two X rows in pattern A (bits 9..7 = k), coalesced
    {
        const float* X0 = X + (size_t)(2 * b) * DIM;
        const float* X1 = X0 + DIM;
        ull ss2 = zero;
        #pragma unroll
        for (int k = 0; k < 8; ++k) {
            int idx = (k << 7) | tid;
            re[k] = pk(X0[idx], X1[idx]);
            im[k] = zero;
            ss2 = fma2(re[k], re[k], ss2);
        }
        float s0, s1; upk(ss2, s0, s1);
        #pragma unroll
        for (int o = 16; o > 0; o >>= 1) {
            s0 += __shfl_xor_sync(0xffffffffu, s0, o);
            s1 += __shfl_xor_sync(0xffffffffu, s1, o);
        }
        if (lane == 0) { red2[warp][0] = s0; red2[warp][1] = s1; }
    }
    __syncthreads();   // gsm + red2 visible
    if (tid == 0) {
        s_inv[0] = 1.f / (red2[0][0] + red2[1][0] + red2[2][0] + red2[3][0]);
        s_inv[1] = 1.f / (red2[0][1] + red2[1][1] + red2[2][1] + red2[3][1]);
    }

    #pragma unroll
    for (int l = 0; l < NL; ++l) {
        const int gb = l * NQ;
        // ---- round A: qubits 0..2 (bits 9..7 = k); CNOT of prev layer folded
        //      into the gather addresses. Cross-quarter -> block barriers.
        if (l == 0) {
            APPLY(gb + 2, 0); APPLY(gb + 1, 1); APPLY(gb + 0, 2);
            #pragma unroll
            for (int k = 0; k < 8; ++k)
                st[swz((k << 7) | tid)] = make_ulonglong2(re[k], im[k]);
        } else {
            __syncthreads();          // prev layer's round-C stores visible
            #pragma unroll
            for (int k = 0; k < 8; ++k) {
                ulonglong2 v = st[g_perm[l - 1][(k << 7) | tid]];  // CNOT folded
                re[k] = v.x; im[k] = v.y;
            }
            APPLY(gb + 2, 0); APPLY(gb + 1, 1); APPLY(gb + 0, 2);
            __syncthreads();          // all gathers done before overwrite
            #pragma unroll
            for (int k = 0; k < 8; ++k)
                st[swz((k << 7) | tid)] = make_ulonglong2(re[k], im[k]);
        }
        // ---- round B: qubits 3..5 (bits 6..4 = k).  addr bits 9..8 = warp id
        //      -> each warp stays inside its own 256-amp quarter.
        __syncthreads();              // round-A cross-quarter scatter visible
        #pragma unroll
        for (int k = 0; k < 8; ++k) {
            ulonglong2 v = st[swz(((tid >> 4) << 7) | (k << 4) | (tid & 15))];
            re[k] = v.x; im[k] = v.y;
        }
        APPLY(gb + 5, 0); APPLY(gb + 4, 1); APPLY(gb + 3, 2);
        #pragma unroll
        for (int k = 0; k < 8; ++k)
            st[swz(((tid >> 4) << 7) | (k << 4) | (tid & 15))] = make_ulonglong2(re[k], im[k]);

        // ---- round C: qubits 6..8 (bits 3..1 = k), qubit 9 (bit 0) via shfl.
        //      Round C also stays inside the same per-warp quarter as round B
        //      (addr bits 9..8 = tid bits 6..5; swizzle touches bits 1..3 only)
        //      -> warp-local ordering is enough.
        __syncwarp();
        #pragma unroll
        for (int k = 0; k < 8; ++k) {
            ulonglong2 v = st[swz(((tid >> 1) << 4) | (k << 1) | (tid & 1))];
            re[k] = v.x; im[k] = v.y;
        }
        APPLY(gb + 8, 0); APPLY(gb + 7, 1); APPLY(gb + 6, 2);
        APPLY_SHFL(gb + 9);
        #pragma unroll
        for (int k = 0; k < 8; ++k)
            st[swz(((tid >> 1) << 4) | (k << 1) | (tid & 1))] = make_ulonglong2(re[k], im[k]);
    }
    __syncthreads();

    // ---- PauliZ expectations; layer-3 perm folded into gather (pattern A)
    ull p[8];
    #pragma unroll
    for (int k = 0; k < 8; ++k) {
        ulonglong2 v = st[g_perm[NL - 1][(k << 7) | tid]];
        p[k] = fma2(v.y, v.y, mul2(v.x, v.x));
    }
    ull T = p[0];
    #pragma unroll
    for (int k = 1; k < 8; ++k) T = add2(T, p[k]);

    ull z[NQ];
    const ull mtwo = pk(-2.f, -2.f);
    #pragma unroll
    for (int q = 0; q < 3; ++q) {            // qubits 0..2 = k bits 2..0
        int bit = 2 - q;
        ull S = zero;
        #pragma unroll
        for (int k = 0; k < 8; ++k)
            if ((k >> bit) & 1) S = add2(S, p[k]);
        z[q] = fma2(mtwo, S, T);             // T - 2*S
    }
    ull nT = neg2(T);
    #pragma unroll
    for (int q = 3; q < NQ; ++q)             // qubits 3..9 = tid bits 6..0
        z[q] = ((tid >> (9 - q)) & 1) ? nT : T;

    #pragma unroll
    for (int q = 0; q < NQ; ++q) {
        #pragma unroll
        for (int o = 16; o > 0; o >>= 1)
            z[q] = add2(z[q], __shfl_xor_sync(0xffffffffu, z[q], o));
        if (lane == 0) zw[warp][q] = z[q];
    }
    __syncthreads();
    if (tid < NQ)
        zsh[tid] = add2(add2(zw[0][tid], zw[1][tid]), add2(zw[2][tid], zw[3][tid]));
    __syncthreads();

    // ---- linear head: 2 batches x 16 outputs on threads 0..31
    if (tid < 32) {
        int bl = tid >> 4, o = tid & 15;
        float inv = s_inv[bl];
        float acc = bias[o];
        #pragma unroll
        for (int q = 0; q < NQ; ++q) {
            float zl, zh; upk(zsh[q], zl, zh);
            acc += inv * (bl ? zh : zl) * W[o * NQ + q];
        }
        out[(size_t)(2 * b + bl) * NOUT + o] = acc;
    }
}

extern "C" void kernel_launch(void* const* d_in, const int* in_sizes, int n_in,
                              void* d_out, int out_size) {
    const float* X    = (const float*)d_in[0];   // (BATCH, 1024) f32
    const float* wts  = (const float*)d_in[1];   // (4, 10, 3) f32
    const float* W    = (const float*)d_in[2];   // (16, 10) f32
    const float* bias = (const float*)d_in[3];   // (16,) f32
    float* out = (float*)d_out;                  // (BATCH, 16) f32

    int batch = in_sizes[0] / DIM;
    vqc_init<<<NL, 256>>>(wts);
    vqc_main<<<batch / 2, TPB>>>(X, W, bias, out);
}

// round 17
// speedup vs baseline: 1.1198x; 1.0015x over previous
#include <cuda_runtime.h>

#define NQ   10
#define DIM  1024
#define NL   4
#define NOUT 16
#define TPB  128

typedef unsigned long long ull;

// Scratch (allocation-free rule: __device__ globals + __constant__)
__device__   ulonglong2     g_gates_stage[NL * NQ * 4];  // init output (staging)
__constant__ ulonglong2     c_gates[NL * NQ * 4];        // 40 gates x 8 packs: G0..G3,N1..N3,pad
__device__   unsigned short g_perm[NL][DIM];             // per-layer perm, PRE-SWIZZLED values

// 16B-granule bank swizzle, bijective on [0,1024); touches only bits 1..3.
__device__ __forceinline__ int swz(int i) { return i ^ (((i >> 4) & 7) << 1); }

// ---- f32x2 packed helpers ----
__device__ __forceinline__ ull pk(float lo, float hi) {
    ull r; asm("mov.b64 %0, {%1, %2};" : "=l"(r) : "f"(lo), "f"(hi)); return r;
}
__device__ __forceinline__ void upk(ull v, float& lo, float& hi) {
    asm("mov.b64 {%0, %1}, %2;" : "=f"(lo), "=f"(hi) : "l"(v));
}
__device__ __forceinline__ ull mul2(ull a, ull b) {
    ull d; asm("mul.rn.f32x2 %0, %1, %2;" : "=l"(d) : "l"(a), "l"(b)); return d;
}
__device__ __forceinline__ ull fma2(ull a, ull b, ull c) {
    ull d; asm("fma.rn.f32x2 %0, %1, %2, %3;" : "=l"(d) : "l"(a), "l"(b), "l"(c)); return d;
}
__device__ __forceinline__ ull add2(ull a, ull b) {
    ull d; asm("add.rn.f32x2 %0, %1, %2;" : "=l"(d) : "l"(a), "l"(b)); return d;
}
__device__ __forceinline__ ull neg2(ull a) { return a ^ 0x8000000080000000ULL; }

// ---------------------------------------------------------------------------
// Init: 8 broadcast packs per gate (negatives precomputed) into staging buffer
// (host side copies to __constant__), + pre-swizzled CNOT permutation tables.
// SU(2): d = conj(a), c = -conj(b).
// ---------------------------------------------------------------------------
__global__ void vqc_init(const float* __restrict__ wts) {
    int l = blockIdx.x;
    int r = l % (NQ - 1) + 1;
    for (int j = threadIdx.x; j < DIM; j += blockDim.x) {
        int t = j;
        #pragma unroll
        for (int q = NQ - 1; q >= 0; --q) {
            int pc = NQ - 1 - q;
            int pt = NQ - 1 - ((q + r) % NQ);
            t ^= ((t >> pc) & 1) << pt;
        }
        g_perm[l][j] = (unsigned short)swz(t);   // pre-swizzled
    }
    if (l == 0 && threadIdx.x < NL * NQ) {
        int idx   = threadIdx.x;
        float phi = wts[idx * 3 + 0];
        float th  = wts[idx * 3 + 1];
        float om  = wts[idx * 3 + 2];
        float sh, ch;   sincosf(0.5f * th, &sh, &ch);
        float ssp, csp; sincosf(0.5f * (phi + om), &ssp, &csp);
        float ssm, csm; sincosf(0.5f * (phi - om), &ssm, &csm);
        float ar =  csp * ch, ai = -ssp * ch;   // a = e^{-i(phi+om)/2} cos
        float br = -csm * sh, bi = -ssm * sh;   // b = -e^{ i(phi-om)/2} sin
        g_gates_stage[idx * 4 + 0] = make_ulonglong2(pk(ar, ar), pk(ai, ai));
        g_gates_stage[idx * 4 + 1] = make_ulonglong2(pk(br, br), pk(bi, bi));
        g_gates_stage[idx * 4 + 2] = make_ulonglong2(pk(-ai, -ai), pk(-br, -br));
        g_gates_stage[idx * 4 + 3] = make_ulonglong2(pk(-bi, -bi), 0ULL);
    }
}

// Complex 2x2 SU(2) gate on batch-packed pair: 16 FFMA2.
__device__ __forceinline__ void cgate(ull G0, ull G1, ull G2, ull G3,
                                      ull N1, ull N2, ull N3,
                                      ull& xr, ull& xi, ull& yr, ull& yi) {
    ull oxr = fma2(N3, yi, fma2(G2, yr, fma2(N1, xi, mul2(G0, xr))));
    ull oxi = fma2(G2, yi, fma2(G3, yr, fma2(G0, xi, mul2(G1, xr))));
    ull oyr = fma2(G1, yi, fma2(G0, yr, fma2(N3, xi, mul2(N2, xr))));
    ull oyi = fma2(G0, yi, fma2(N1, yr, fma2(N2, xi, mul2(G3, xr))));
    xr = oxr; xi = oxi; yr = oyr; yi = oyi;
}

// Apply gate `gid` to local k-bit m over the 8-amp register tile.
// Coefficients come from the constant bank (LDC broadcast, off the LSU port).
#define APPLY(gid, m)                                                          \
    do {                                                                       \
        ulonglong2 _u0 = c_gates[(gid) * 4 + 0], _u1 = c_gates[(gid) * 4 + 1]; \
        ulonglong2 _u2 = c_gates[(gid) * 4 + 2], _u3 = c_gates[(gid) * 4 + 3]; \
        ull _G0 = _u0.x, _G1 = _u0.y, _G2 = _u1.x, _G3 = _u1.y;                \
        ull _N1 = _u2.x, _N2 = _u2.y, _N3 = _u3.x;                             \
        _Pragma("unroll")                                                      \
        for (int _p = 0; _p < 4; ++_p) {                                       \
            int _i = ((_p >> (m)) << ((m) + 1)) | (_p & ((1 << (m)) - 1));     \
            int _j = _i | (1 << (m));                                          \
            cgate(_G0,_G1,_G2,_G3,_N1,_N2,_N3, re[_i], im[_i], re[_j], im[_j]);\
        }                                                                      \
    } while (0)

// Gate on lane bit 0 (qubit 9) via warp shuffle; each thread computes its half.
#define APPLY_SHFL(gid)                                                        \
    do {                                                                       \
        ulonglong2 _u0 = c_gates[(gid) * 4 + 0], _u1 = c_gates[(gid) * 4 + 1]; \
        ulonglong2 _u2 = c_gates[(gid) * 4 + 2], _u3 = c_gates[(gid) * 4 + 3]; \
        ull _G0 = _u0.x, _G1 = _u0.y, _G2 = _u1.x, _G3 = _u1.y;                \
        ull _N1 = _u2.x, _N2 = _u2.y, _N3 = _u3.x;                             \
        int _s = tid & 1;                                                      \
        ull _c1r = _G0;                                                        \
        ull _c1i = _s ? _N1 : _G1;                                             \
        ull _n1i = _s ? _G1 : _N1;                                             \
        ull _c2r = _s ? _N2 : _G2;                                             \
        ull _c2i = _G3, _n2i = _N3;                                            \
        _Pragma("unroll")                                                      \
        for (int _k = 0; _k < 8; ++_k) {                                       \
            ull _vr = re[_k], _vi = im[_k];                                    \
            ull _ur = __shfl_xor_sync(0xffffffffu, _vr, 1);                    \
            ull _ui = __shfl_xor_sync(0xffffffffu, _vi, 1);                    \
            re[_k] = fma2(_n2i,_ui, fma2(_c2r,_ur, fma2(_n1i,_vi, mul2(_c1r,_vr)))); \
            im[_k] = fma2(_c2i,_ur, fma2(_c2r,_ui, fma2(_c1i,_vr, mul2(_c1r,_vi)))); \
        }                                                                      \
    } while (0)

__global__ void __launch_bounds__(TPB, 7) vqc_main(
    const float* __restrict__ X,
    const float* __restrict__ W,
    const float* __restrict__ bias,
    float* __restrict__ out)
{
    __shared__ ulonglong2 st[DIM];            // batch-pair state (16 KB), swizzled
    __shared__ ull        zw[4][NQ];
    __shared__ ull        zsh[NQ];
    __shared__ float      red2[4][2];
    __shared__ float      s_inv[2];

    const int tid  = threadIdx.x;
    const int b    = blockIdx.x;
    const int lane = tid & 31, warp = tid >> 5;

    ull re[8], im[8];
    const ull zero = pk(0.f, 0.f);

    // ---- load two X rows in pattern A (bits 9..7 = k), coalesced
    {
        const float* X0 = X + (size_t)(2 * b) * DIM;
        const float* X1 = X0 + DIM;
        ull ss2 = zero;
        #pragma unroll
        for (int k = 0; k < 8; ++k) {
            int idx = (k << 7) | tid;
            re[k] = pk(X0[idx], X1[idx]);
            im[k] = zero;
            ss2 = fma2(re[k], re[k], ss2);
        }
        float s0, s1; upk(ss2, s0, s1);
        #pragma unroll
        for (int o = 16; o > 0; o >>= 1) {
            s0 += __shfl_xor_sync(0xffffffffu, s0, o);
            s1 += __shfl_xor_sync(0xffffffffu, s1, o);
        }
        if (lane == 0) { red2[warp][0] = s0; red2[warp][1] = s1; }
    }
    __syncthreads();   // red2 visible
    if (tid == 0) {
        s_inv[0] = 1.f / (red2[0][0] + red2[1][0] + red2[2][0] + red2[3][0]);
        s_inv[1] = 1.f / (red2[0][1] + red2[1][1] + red2[2][1] + red2[3][1]);
    }

    #pragma unroll
    for (int l = 0; l < NL; ++l) {
        const int gb = l * NQ;
        // ---- round A: qubits 0..2 (bits 9..7 = k); CNOT of prev layer folded
        //      into the gather addresses. Cross-quarter -> block barriers.
        if (l == 0) {
            APPLY(gb + 2, 0); APPLY(gb + 1, 1); APPLY(gb + 0, 2);
            #pragma unroll
            for (int k = 0; k < 8; ++k)
                st[swz((k << 7) | tid)] = make_ulonglong2(re[k], im[k]);
        } else {
            __syncthreads();          // prev layer's round-C stores visible
            #pragma unroll
            for (int k = 0; k < 8; ++k) {
                ulonglong2 v = st[g_perm[l - 1][(k << 7) | tid]];  // CNOT folded
                re[k] = v.x; im[k] = v.y;
            }
            APPLY(gb + 2, 0); APPLY(gb + 1, 1); APPLY(gb + 0, 2);
            __syncthreads();          // all gathers done before overwrite
            #pragma unroll
            for (int k = 0; k < 8; ++k)
                st[swz((k << 7) | tid)] = make_ulonglong2(re[k], im[k]);
        }
        // ---- round B: qubits 3..5 (bits 6..4 = k).  addr bits 9..8 = warp id
        //      -> each warp stays inside its own 256-amp quarter.
        __syncthreads();              // round-A cross-quarter scatter visible
        #pragma unroll
        for (int k = 0; k < 8; ++k) {
            ulonglong2 v = st[swz(((tid >> 4) << 7) | (k << 4) | (tid & 15))];
            re[k] = v.x; im[k] = v.y;
        }
        APPLY(gb + 5, 0); APPLY(gb + 4, 1); APPLY(gb + 3, 2);
        #pragma unroll
        for (int k = 0; k < 8; ++k)
            st[swz(((tid >> 4) << 7) | (k << 4) | (tid & 15))] = make_ulonglong2(re[k], im[k]);

        // ---- round C: qubits 6..8 (bits 3..1 = k), qubit 9 (bit 0) via shfl.
        //      Same per-warp quarter as round B -> warp-local ordering suffices.
        __syncwarp();
        #pragma unroll
        for (int k = 0; k < 8; ++k) {
            ulonglong2 v = st[swz(((tid >> 1) << 4) | (k << 1) | (tid & 1))];
            re[k] = v.x; im[k] = v.y;
        }
        APPLY(gb + 8, 0); APPLY(gb + 7, 1); APPLY(gb + 6, 2);
        APPLY_SHFL(gb + 9);
        #pragma unroll
        for (int k = 0; k < 8; ++k)
            st[swz(((tid >> 1) << 4) | (k << 1) | (tid & 1))] = make_ulonglong2(re[k], im[k]);
    }
    __syncthreads();

    // ---- PauliZ expectations; layer-3 perm folded into gather (pattern A)
    ull p[8];
    #pragma unroll
    for (int k = 0; k < 8; ++k) {
        ulonglong2 v = st[g_perm[NL - 1][(k << 7) | tid]];
        p[k] = fma2(v.y, v.y, mul2(v.x, v.x));
    }
    ull T = p[0];
    #pragma unroll
    for (int k = 1; k < 8; ++k) T = add2(T, p[k]);

    ull z[NQ];
    const ull mtwo = pk(-2.f, -2.f);
    #pragma unroll
    for (int q = 0; q < 3; ++q) {            // qubits 0..2 = k bits 2..0
        int bit = 2 - q;
        ull S = zero;
        #pragma unroll
        for (int k = 0; k < 8; ++k)
            if ((k >> bit) & 1) S = add2(S, p[k]);
        z[q] = fma2(mtwo, S, T);             // T - 2*S
    }
    ull nT = neg2(T);
    #pragma unroll
    for (int q = 3; q < NQ; ++q)             // qubits 3..9 = tid bits 6..0
        z[q] = ((tid >> (9 - q)) & 1) ? nT : T;

    #pragma unroll
    for (int q = 0; q < NQ; ++q) {
        #pragma unroll
        for (int o = 16; o > 0; o >>= 1)
            z[q] = add2(z[q], __shfl_xor_sync(0xffffffffu, z[q], o));
        if (lane == 0) zw[warp][q] = z[q];
    }
    __syncthreads();
    if (tid < NQ)
        zsh[tid] = add2(add2(zw[0][tid], zw[1][tid]), add2(zw[2][tid], zw[3][tid]));
    __syncthreads();

    // ---- linear head: 2 batches x 16 outputs on threads 0..31
    if (tid < 32) {
        int bl = tid >> 4, o = tid & 15;
        float inv = s_inv[bl];
        float acc = bias[o];
        #pragma unroll
        for (int q = 0; q < NQ; ++q) {
            float zl, zh; upk(zsh[q], zl, zh);
            acc += inv * (bl ? zh : zl) * W[o * NQ + q];
        }
        out[(size_t)(2 * b + bl) * NOUT + o] = acc;
    }
}

extern "C" void kernel_launch(void* const* d_in, const int* in_sizes, int n_in,
                              void* d_out, int out_size) {
    const float* X    = (const float*)d_in[0];   // (BATCH, 1024) f32
    const float* wts  = (const float*)d_in[1];   // (4, 10, 3) f32
    const float* W    = (const float*)d_in[2];   // (16, 10) f32
    const float* bias = (const float*)d_in[3];   // (16,) f32
    float* out = (float*)d_out;                  // (BATCH, 16) f32

    int batch = in_sizes[0] / DIM;
    vqc_init<<<NL, 256>>>(wts);
    // Publish gate packs to the constant bank (graph-capturable: async D2D)
    void* stage_ptr = nullptr;
    cudaGetSymbolAddress(&stage_ptr, g_gates_stage);
    cudaMemcpyToSymbolAsync(c_gates, stage_ptr, sizeof(ulonglong2) * NL * NQ * 4,
                            0, cudaMemcpyDeviceToDevice, 0);
    vqc_main<<<batch / 2, TPB>>>(X, W, bias, out);
}